// round 10
// baseline (speedup 1.0000x reference)
#include <cuda_runtime.h>
#include <cstdint>

// 2-bit quantized embedding lookup — warp processes 16 tokens (MLP=16),
// id-dtype detection folded into the main kernel (no pre-kernel).
// ids: [262144] (int32 OR int64, runtime-detected), bit_arr: [3.2M] int32,
// codebook: [4] float. Token's 128 codes = 8 aligned int32 words at bit_arr[tok*8].
//
// Per warp: lane l loads id[wbase+(l&15)]; shfl(width=16) broadcasts 16 ids;
// 16 independent bit-word loads issue back to back (hides L2/DRAM latency);
// then 16 decode+store rounds, each a coalesced 512B STG.128.CS burst
// (4 full 128B lines, streaming/evict-first so the output doesn't thrash the
// L2-resident bit_arr). Lane l owns dims 4l..4l+3 of each token.

#define TPW 16   // tokens per warp

__device__ __forceinline__ float4 decode16(unsigned b,
                                           float c0, float c1, float c2, float c3)
{
    float4 v;
    {
        unsigned code = b & 3u;
        float a = (code & 1u) ? c1 : c0;
        float d = (code & 1u) ? c3 : c2;
        v.x = (code & 2u) ? d : a;
    }
    {
        unsigned code = (b >> 2) & 3u;
        float a = (code & 1u) ? c1 : c0;
        float d = (code & 1u) ? c3 : c2;
        v.y = (code & 2u) ? d : a;
    }
    {
        unsigned code = (b >> 4) & 3u;
        float a = (code & 1u) ? c1 : c0;
        float d = (code & 1u) ? c3 : c2;
        v.z = (code & 2u) ? d : a;
    }
    {
        unsigned code = (b >> 6) & 3u;
        float a = (code & 1u) ? c1 : c0;
        float d = (code & 1u) ? c3 : c2;
        v.w = (code & 2u) ? d : a;
    }
    return v;
}

__global__ void __launch_bounds__(256) embed2b_kernel(
    const unsigned* __restrict__ idw,   // ids viewed as 32-bit words
    const unsigned* __restrict__ bits,
    const float*    __restrict__ cb,
    float4*         __restrict__ out,
    int n_tokens)
{
    int gt    = blockIdx.x * blockDim.x + threadIdx.x;
    int lane  = threadIdx.x & 31;
    int wbase = (gt >> 5) * TPW;        // first token of this warp

    // ---- in-warp id-dtype detection (2 cache lines, broadcast hits) ----
    // int64 ids (nonneg < 2^31): odd 32-bit words 1..63 are all zero.
    // int32 ids: those words are 32 random ids; all-zero prob ~ (2.5e-6)^32.
    unsigned oddw = __ldg(idw + 2 * lane + 1);
    int stride = __any_sync(0xffffffffu, oddw != 0u) ? 1 : 2;

    if (wbase >= n_tokens) return;

    float c0 = __ldg(cb + 0);
    float c1 = __ldg(cb + 1);
    float c2 = __ldg(cb + 2);
    float c3 = __ldg(cb + 3);

    int wsel = lane >> 2;               // which packed word this lane needs
    int bsh  = (lane & 3) * 8;          // byte shift within that word

    if (wbase + TPW <= n_tokens) {
        // ---- fast path: full group of 16 tokens ----
        // lane l holds id of token wbase + (l&15); low word = full value (LE)
        unsigned myid = __ldg(idw + (size_t)(wbase + (lane & (TPW - 1))) * stride);

        unsigned w[TPW];
        #pragma unroll
        for (int t = 0; t < TPW; t++) {         // 16 independent loads, MLP=16
            unsigned tok = __shfl_sync(0xffffffffu, myid, t, TPW);
            w[t] = __ldg(bits + tok * 8u + wsel);
        }

        #pragma unroll
        for (int t = 0; t < TPW; t++) {
            float4 v = decode16(w[t] >> bsh, c0, c1, c2, c3);
            // streaming store: 4 full 128B lines/warp, evict-first in L2
            __stcs(out + (size_t)(wbase + t) * 32 + lane, v);
        }
    } else {
        // ---- tail: per-token ----
        for (int t = 0; t < TPW && wbase + t < n_tokens; t++) {
            unsigned tok = __ldg(idw + (size_t)(wbase + t) * stride);
            unsigned wv  = __ldg(bits + tok * 8u + wsel);
            float4 v = decode16(wv >> bsh, c0, c1, c2, c3);
            __stcs(out + (size_t)(wbase + t) * 32 + lane, v);
        }
    }
}

extern "C" void kernel_launch(void* const* d_in, const int* in_sizes, int n_in,
                              void* d_out, int out_size)
{
    const unsigned* idw  = (const unsigned*)d_in[0];  // ids (int32 or int64)
    const unsigned* bits = (const unsigned*)d_in[1];  // packed 2-bit codes
    const float*    cb   = (const float*)d_in[2];     // 4-entry codebook
    float*          out  = (float*)d_out;             // [N, 128] fp32

    int n_tokens = in_sizes[0];                        // 64*4096 = 262144

    int warps  = (n_tokens + TPW - 1) / TPW;
    long long total_threads = (long long)warps * 32;
    int block = 256;
    int grid = (int)((total_threads + block - 1) / block);
    embed2b_kernel<<<grid, block>>>(idw, bits, cb, (float4*)out, n_tokens);
}